// round 7
// baseline (speedup 1.0000x reference)
#include <cuda_runtime.h>
#include <math.h>

// Problem constants
#define BATCH 32
#define NSEQ  1024
#define DDIM  512
#define NHEAD 8
#define SCALE 0.04419417382415922f   // 1/sqrt(512)

// ---------------------------------------------------------------------------
// Scratch (device globals; allocation-free per harness rules)
// ---------------------------------------------------------------------------
__device__ float g_kr [(size_t)BATCH * NSEQ * DDIM];
__device__ float g_vr [(size_t)BATCH * NSEQ * DDIM];
__device__ float g_qr [(size_t)BATCH * NSEQ * DDIM];
__device__ float g_wkr[(size_t)NHEAD * DDIM * DDIM];
__device__ float g_wvr[(size_t)NHEAD * DDIM * DDIM];
__device__ float g_wqr[(size_t)NHEAD * DDIM * DDIM];
__device__ float g_kh [(size_t)BATCH * NHEAD * NSEQ * DDIM];
__device__ float g_vh [(size_t)BATCH * NHEAD * NSEQ * DDIM];
__device__ float g_qh [(size_t)BATCH * NHEAD * NSEQ * DDIM];  // pre-scaled by 1/sqrt(D)
__device__ float g_att[(size_t)BATCH * NHEAD * NSEQ * DDIM];
__device__ float g_wot[(size_t)NHEAD * DDIM * DDIM];

#define NTHREADS 256
#define STAGE_BYTES 32768u
#define SMEM_BYTES (3 * STAGE_BYTES)       // GEMM kernels: 96KB

// Flash kernel smem layout (bytes)
#define QB 64
#define JT 128
#define QS_OFF   0u                         // 64x512 tf32, 16 chunks [64][32]
#define PS_OFF   131072u                    // 64x128 tf32, 4 chunks [64][32]
#define KV_OFF   163840u                    // 3 bufs x 16640
#define KV_STRIDE 16640u
#define REDM_OFF 213760u
#define REDL_OFF 214784u
#define MROW_OFF 215808u
#define LROW_OFF 216064u
#define AROW_OFF 216320u
#define MNEW_OFF 216576u
#define SMEM_FLASH 216832u

// ---------------------------------------------------------------------------
// Primitives
// ---------------------------------------------------------------------------
__device__ __forceinline__ unsigned f2tf(float f) {
    unsigned u;
    asm("cvt.rna.tf32.f32 %0, %1;" : "=r"(u) : "f"(f));
    return u;
}
__device__ __forceinline__ float rf(float f) { return __uint_as_float(f2tf(f)); }

__device__ __forceinline__ void store2r(float* p, float x, float y) {
    *(float2*)p = make_float2(rf(x), rf(y));
}

__device__ __forceinline__ void mma_tf32(float* d, const unsigned* a, const unsigned* b) {
    asm volatile(
        "mma.sync.aligned.m16n8k8.row.col.f32.tf32.tf32.f32 "
        "{%0,%1,%2,%3}, {%4,%5,%6,%7}, {%8,%9}, {%0,%1,%2,%3};\n"
        : "+f"(d[0]), "+f"(d[1]), "+f"(d[2]), "+f"(d[3])
        : "r"(a[0]), "r"(a[1]), "r"(a[2]), "r"(a[3]), "r"(b[0]), "r"(b[1]));
}

__device__ __forceinline__ void ldsm4(unsigned d[4], unsigned addr) {
    asm volatile("ldmatrix.sync.aligned.m8n8.x4.shared.b16 {%0,%1,%2,%3}, [%4];"
                 : "=r"(d[0]), "=r"(d[1]), "=r"(d[2]), "=r"(d[3]) : "r"(addr));
}

__device__ __forceinline__ void cp16(unsigned dst, const float* src) {
    asm volatile("cp.async.cg.shared.global [%0], [%1], 16;" :: "r"(dst), "l"(src));
}
#define CP_COMMIT() asm volatile("cp.async.commit_group;")
#define CP_WAIT1()  asm volatile("cp.async.wait_group 1;")

#define ZERO_ACC(acc)                          \
    _Pragma("unroll")                          \
    for (int mi = 0; mi < 4; mi++)             \
    _Pragma("unroll")                          \
    for (int ni = 0; ni < 4; ni++)             \
    _Pragma("unroll")                          \
    for (int q = 0; q < 4; q++) acc[mi][ni][q] = 0.f;

// Stage one 128-row x 32-word tile via cp.async, XOR-4 swizzled.
__device__ __forceinline__ void stage_tile(unsigned sb, const float* src, size_t ld,
                                           int sr, int sc4, int xs) {
#pragma unroll
    for (int p = 0; p < 4; p++) {
        const int r = sr + p * 32;
        const unsigned dst = sb + (((r << 5) + (sc4 ^ xs)) << 2);
        cp16(dst, src + (size_t)r * ld + sc4);
    }
}

// ---------------------------------------------------------------------------
// GEMM core for proj/outproj (unchanged from R5, proven)
// ---------------------------------------------------------------------------
__device__ __forceinline__ void tile_compute(unsigned bufA, float acc[4][4][4],
                                             int wm, int wn, int rA, int aoff, int xrA,
                                             int rB, int boff, int xrB) {
    const unsigned bufB = bufA + 16384u;
#pragma unroll
    for (int ks = 0; ks < 4; ks++) {
        unsigned a[4][4], b[2][4];
        const int ca = ((ks << 3) + aoff) ^ xrA;
        const int cb = ((ks << 3) + boff) ^ xrB;
#pragma unroll
        for (int mi = 0; mi < 4; mi++)
            ldsm4(a[mi], bufA + ((((wm + mi * 16 + rA) << 5) + ca) << 2));
#pragma unroll
        for (int p = 0; p < 2; p++)
            ldsm4(b[p], bufB + ((((wn + p * 16 + rB) << 5) + cb) << 2));
#pragma unroll
        for (int mi = 0; mi < 4; mi++)
#pragma unroll
            for (int ni = 0; ni < 4; ni++)
                mma_tf32(acc[mi][ni], a[mi], &b[ni >> 1][(ni & 1) << 1]);
    }
}

__device__ __forceinline__ void gemm_loop(unsigned sbase,
                                          const float* pA, size_t ldA,
                                          const float* pB, size_t ldB,
                                          int KT, unsigned aMask, size_t aBig,
                                          float acc[4][4][4]) {
    const int tid = threadIdx.x;
    const int lane = tid & 31, warp = tid >> 5;
    const int wm = (warp >> 2) * 64, wn = (warp & 3) * 32;
    const int sr = tid >> 3, sc4 = (tid & 7) << 2, xs = (sr & 7) << 2;
    const int rA = lane & 15;
    const int aoff = (lane >> 4) << 2;
    const int xrA = (rA & 7) << 2;
    const int rB = ((lane >> 4) << 3) + (lane & 7);
    const int boff = ((lane >> 3) & 1) << 2;
    const int xrB = (lane & 7) << 2;

    unsigned s0 = sbase, s1 = sbase + STAGE_BYTES, s2 = sbase + 2 * STAGE_BYTES;

    stage_tile(s0, pA, ldA, sr, sc4, xs);
    stage_tile(s0 + 16384u, pB, ldB, sr, sc4, xs);
    CP_COMMIT();
    pA += ((1u & aMask) == 0u) ? aBig : 32;
    pB += 32;
    stage_tile(s1, pA, ldA, sr, sc4, xs);
    stage_tile(s1 + 16384u, pB, ldB, sr, sc4, xs);
    CP_COMMIT();

    for (int kt = 0; kt < KT; kt++) {
        CP_WAIT1();
        __syncthreads();
        if (kt + 2 < KT) {
            pA += (((unsigned)(kt + 2) & aMask) == 0u) ? aBig : 32;
            pB += 32;
            stage_tile(s2, pA, ldA, sr, sc4, xs);
            stage_tile(s2 + 16384u, pB, ldB, sr, sc4, xs);
        }
        CP_COMMIT();
        tile_compute(s0, acc, wm, wn, rA, aoff, xrA, rB, boff, xrB);
        const unsigned t = s0; s0 = s1; s1 = s2; s2 = t;
    }
}

// ---------------------------------------------------------------------------
// Pre-pass kernels
// ---------------------------------------------------------------------------
template <int T>
__global__ void round_copy_kernel(const float* __restrict__ src, int n4)
{
    float* dst = (T == 0) ? g_kr : (T == 1) ? g_vr : (T == 2) ? g_qr
               : (T == 3) ? g_wkr : (T == 4) ? g_wvr : g_wqr;
    int i = blockIdx.x * blockDim.x + threadIdx.x;
    if (i < n4) {
        float4 v = ((const float4*)src)[i];
        ((float4*)dst)[i] = make_float4(rf(v.x), rf(v.y), rf(v.z), rf(v.w));
    }
}

__global__ void permute_wo_kernel(const float* __restrict__ Wo)
{
    int idx = blockIdx.x * blockDim.x + threadIdx.x;   // dd*4096 + h*512 + e
    int t  = idx & (NHEAD * DDIM - 1);
    int dd = idx >> 12;
    int e  = t & (DDIM - 1);
    int h  = t >> 9;
    g_wot[idx] = rf(Wo[(size_t)dd * (NHEAD * DDIM) + e * NHEAD + h]);
}

// ---------------------------------------------------------------------------
// Projection (NT): Y[b,h,n,e] = X.W^T + bias (rounded). P==2 pre-scales Q.
// ---------------------------------------------------------------------------
template <int P>
__global__ __launch_bounds__(NTHREADS, 2)
void proj_kernel(const float* __restrict__ bias)
{
    extern __shared__ __align__(16) unsigned char smem[];
    const unsigned sbase = (unsigned)__cvta_generic_to_shared(smem);

    const float* X = (P == 0) ? g_kr : (P == 1) ? g_vr : g_qr;
    const float* W = (P == 0) ? g_wkr : (P == 1) ? g_wvr : g_wqr;
    float* Y = (P == 0) ? g_kh : (P == 1) ? g_vh : g_qh;
    const float postscale = (P == 2) ? SCALE : 1.0f;

    const int h = blockIdx.z, m0 = blockIdx.x * 128, e0 = blockIdx.y * 128;

    float acc[4][4][4];
    ZERO_ACC(acc);
    gemm_loop(sbase, X + (size_t)m0 * DDIM, DDIM,
              W + (size_t)h * DDIM * DDIM + (size_t)e0 * DDIM, DDIM,
              DDIM / 32, 0u, 32, acc);

    const int lane = threadIdx.x & 31, warp = threadIdx.x >> 5;
    const int wm = (warp >> 2) * 64, wn = (warp & 3) * 32;
    const int g = lane >> 2, tg = lane & 3;
    const int bb = m0 / NSEQ, n0 = m0 % NSEQ;
    float* Yb = Y + (((size_t)bb * NHEAD + h) * NSEQ + n0) * DDIM + e0;
    const float* bh = bias + h * DDIM + e0;
#pragma unroll
    for (int mi = 0; mi < 4; mi++) {
        const int r = wm + mi * 16 + g;
#pragma unroll
        for (int ni = 0; ni < 4; ni++) {
            const int c = wn + ni * 8 + tg * 2;
            const float b0 = bh[c], b1 = bh[c + 1];
            store2r(Yb + (size_t)r * DDIM + c,
                    (acc[mi][ni][0] + b0) * postscale, (acc[mi][ni][1] + b1) * postscale);
            store2r(Yb + (size_t)(r + 8) * DDIM + c,
                    (acc[mi][ni][2] + b0) * postscale, (acc[mi][ni][3] + b1) * postscale);
        }
    }
}

// ---------------------------------------------------------------------------
// Flash attention: per CTA (z, 64 Q-rows): online softmax over 8 j-tiles.
// Q resident in smem; K streamed (QK phase); V streamed natural-layout (PV).
// Output: g_att[z][i][e] = softmax(QK^T)V, rounded to tf32.
// ---------------------------------------------------------------------------
__global__ __launch_bounds__(NTHREADS, 1)
void flash_kernel()
{
    extern __shared__ __align__(16) unsigned char smem[];
    const unsigned sb = (unsigned)__cvta_generic_to_shared(smem);
    const unsigned QS = sb + QS_OFF;
    const unsigned PS = sb + PS_OFF;
    const unsigned KV = sb + KV_OFF;
    float* redM = (float*)(smem + REDM_OFF);
    float* redL = (float*)(smem + REDL_OFF);
    float* mrow = (float*)(smem + MROW_OFF);
    float* lrow = (float*)(smem + LROW_OFF);
    float* arow = (float*)(smem + AROW_OFF);
    float* mnew = (float*)(smem + MNEW_OFF);
    unsigned* Pw = (unsigned*)(smem + PS_OFF);
    const unsigned* Vw = (const unsigned*)(smem + KV_OFF);

    const int z = blockIdx.y;
    const int i0 = blockIdx.x * QB;
    const float* Qz = g_qh + (size_t)z * NSEQ * DDIM + (size_t)i0 * DDIM;
    const float* Kz = g_kh + (size_t)z * NSEQ * DDIM;
    const float* Vz = g_vh + (size_t)z * NSEQ * DDIM;

    const int tid = threadIdx.x, lane = tid & 31, warp = tid >> 5;
    const int wmq = (warp >> 2) * 32, wnq = (warp & 3) * 32;  // QK: 2m x 4n
    const int wne = warp * 64;                                 // PV: 1m x 8n
    const int g = lane >> 2, tg = lane & 3;
    const int rA = lane & 15, aoff = (lane >> 4) << 2, xrA = (rA & 7) << 2;
    const int rB = ((lane >> 4) << 3) + (lane & 7);
    const int boff = ((lane >> 3) & 1) << 2, xrB = (lane & 7) << 2;
    const int sr = tid >> 3, sc4 = (tid & 7) << 2, xs = (sr & 7) << 2;
    const int vr = tid >> 5, vc4 = (tid & 31) << 2;

    if (tid < QB) { mrow[tid] = -1e30f; lrow[tid] = 0.f; }

    // Stage Q resident: 16 chunks of [64][32], swizzled (one cp group).
    {
        const int r0 = tid >> 3, c4 = (tid & 7) << 2;
#pragma unroll 4
        for (int c = 0; c < 16; c++) {
            const unsigned cb = QS + (unsigned)c * 8192u;
#pragma unroll
            for (int p = 0; p < 2; p++) {
                const int r = r0 + p * 32;
                cp16(cb + (((r << 5) + (c4 ^ ((r & 7) << 2))) << 2),
                     Qz + (size_t)r * DDIM + c * 32 + c4);
            }
        }
    }
    CP_COMMIT();

    float O[4][8][4];
#pragma unroll
    for (int mi = 0; mi < 4; mi++)
#pragma unroll
        for (int ni = 0; ni < 8; ni++)
#pragma unroll
            for (int q = 0; q < 4; q++) O[mi][ni][q] = 0.f;

    for (int jt = 0; jt < 8; jt++) {
        const float* Kj = Kz + (size_t)jt * JT * DDIM;
        const float* Vj = Vz + (size_t)jt * JT * DDIM;

        // ---- QK phase: S = Q . Kj^T over 16 d-chunks ----
        stage_tile(KV + 0u * KV_STRIDE, Kj, DDIM, sr, sc4, xs);
        CP_COMMIT();
        stage_tile(KV + 1u * KV_STRIDE, Kj + 32, DDIM, sr, sc4, xs);
        CP_COMMIT();

        float S[2][4][4];
#pragma unroll
        for (int mi = 0; mi < 2; mi++)
#pragma unroll
            for (int ni = 0; ni < 4; ni++)
#pragma unroll
                for (int q = 0; q < 4; q++) S[mi][ni][q] = 0.f;

        for (int c = 0; c < 16; c++) {
            CP_WAIT1();
            __syncthreads();
            if (c + 2 < 16)
                stage_tile(KV + (unsigned)((c + 2) % 3) * KV_STRIDE,
                           Kj + (c + 2) * 32, DDIM, sr, sc4, xs);
            CP_COMMIT();
            const unsigned Ab = QS + (unsigned)c * 8192u;
            const unsigned Bb = KV + (unsigned)(c % 3) * KV_STRIDE;
#pragma unroll
            for (int ks = 0; ks < 4; ks++) {
                unsigned a[2][4], b[2][4];
                const int ca = ((ks << 3) + aoff) ^ xrA;
                const int cb = ((ks << 3) + boff) ^ xrB;
#pragma unroll
                for (int mi = 0; mi < 2; mi++)
                    ldsm4(a[mi], Ab + ((((wmq + mi * 16 + rA) << 5) + ca) << 2));
#pragma unroll
                for (int p = 0; p < 2; p++)
                    ldsm4(b[p], Bb + ((((wnq + p * 16 + rB) << 5) + cb) << 2));
#pragma unroll
                for (int mi = 0; mi < 2; mi++)
#pragma unroll
                    for (int ni = 0; ni < 4; ni++)
                        mma_tf32(S[mi][ni], a[mi], &b[ni >> 1][(ni & 1) << 1]);
            }
        }

        // ---- online softmax ----
        // warp-local row maxima over this warp's 32 cols
        float pm[2][2];
#pragma unroll
        for (int mi = 0; mi < 2; mi++)
#pragma unroll
            for (int q = 0; q < 2; q++) {
                float m = -1e30f;
#pragma unroll
                for (int ni = 0; ni < 4; ni++)
                    m = fmaxf(m, fmaxf(S[mi][ni][2 * q], S[mi][ni][2 * q + 1]));
                pm[mi][q] = m;
            }
#pragma unroll
        for (int o = 1; o <= 2; o <<= 1)
#pragma unroll
            for (int mi = 0; mi < 2; mi++)
#pragma unroll
                for (int q = 0; q < 2; q++)
                    pm[mi][q] = fmaxf(pm[mi][q], __shfl_xor_sync(0xffffffffu, pm[mi][q], o));
        if ((lane & 3) == 0) {
#pragma unroll
            for (int mi = 0; mi < 2; mi++)
#pragma unroll
                for (int q = 0; q < 2; q++)
                    redM[(warp & 3) * 64 + wmq + mi * 16 + g + 8 * q] = pm[mi][q];
        }
        __syncthreads();
        if (tid < QB) {
            float Mt = fmaxf(fmaxf(redM[tid], redM[64 + tid]),
                             fmaxf(redM[128 + tid], redM[192 + tid]));
            float mo = mrow[tid];
            float mn = fmaxf(mo, Mt);
            mnew[tid] = mn;
            arow[tid] = __expf(mo - mn);
        }
        __syncthreads();

        // p = exp(s - m_new): store rf(p) to Ps, accumulate row sums
        float psum[2][2] = {{0.f, 0.f}, {0.f, 0.f}};
#pragma unroll
        for (int mi = 0; mi < 2; mi++)
#pragma unroll
            for (int q = 0; q < 2; q++) {
                const int row = wmq + mi * 16 + g + 8 * q;
                const float mn = mnew[row];
                const int xsr = (row & 7) << 2;
#pragma unroll
                for (int ni = 0; ni < 4; ni++) {
                    const int c0 = ni * 8 + tg * 2;
                    float p0 = __expf(S[mi][ni][2 * q] - mn);
                    float p1 = __expf(S[mi][ni][2 * q + 1] - mn);
                    psum[mi][q] += p0 + p1;
                    const int base = (warp & 3) * 2048 + row * 32;
                    Pw[base + (c0 ^ xsr)] = f2tf(p0);
                    Pw[base + ((c0 + 1) ^ xsr)] = f2tf(p1);
                }
            }
#pragma unroll
        for (int o = 1; o <= 2; o <<= 1)
#pragma unroll
            for (int mi = 0; mi < 2; mi++)
#pragma unroll
                for (int q = 0; q < 2; q++)
                    psum[mi][q] += __shfl_xor_sync(0xffffffffu, psum[mi][q], o);
        if ((lane & 3) == 0) {
#pragma unroll
            for (int mi = 0; mi < 2; mi++)
#pragma unroll
                for (int q = 0; q < 2; q++)
                    redL[(warp & 3) * 64 + wmq + mi * 16 + g + 8 * q] = psum[mi][q];
        }

        // rescale O by alpha (arow stable until next tile)
#pragma unroll
        for (int mi = 0; mi < 4; mi++) {
            const float a0 = arow[mi * 16 + g], a1 = arow[mi * 16 + g + 8];
#pragma unroll
            for (int ni = 0; ni < 8; ni++) {
                O[mi][ni][0] *= a0; O[mi][ni][1] *= a0;
                O[mi][ni][2] *= a1; O[mi][ni][3] *= a1;
            }
        }
        __syncthreads();
        if (tid < QB) {
            float Lt = redL[tid] + redL[64 + tid] + redL[128 + tid] + redL[192 + tid];
            lrow[tid] = lrow[tid] * arow[tid] + Lt;
            mrow[tid] = mnew[tid];
        }
        __syncthreads();   // Ps + stats complete before PV reads

        // ---- PV phase: O += P . Vj, 16 k8-steps, V chunks of 8 rows ----
#pragma unroll
        for (int p = 0; p < 4; p++)
            cp16(KV + 0u * KV_STRIDE + (((vr * 520) + vc4 + p * 128) << 2),
                 Vj + (size_t)vr * DDIM + vc4 + p * 128);
        CP_COMMIT();
#pragma unroll
        for (int p = 0; p < 4; p++)
            cp16(KV + 1u * KV_STRIDE + (((vr * 520) + vc4 + p * 128) << 2),
                 Vj + (size_t)(8 + vr) * DDIM + vc4 + p * 128);
        CP_COMMIT();

        for (int s = 0; s < 16; s++) {
            CP_WAIT1();
            __syncthreads();
            if (s + 2 < 16) {
                const unsigned vb = KV + (unsigned)((s + 2) % 3) * KV_STRIDE;
                const float* vsrc = Vj + (size_t)((s + 2) * 8 + vr) * DDIM;
#pragma unroll
                for (int p = 0; p < 4; p++)
                    cp16(vb + (((vr * 520) + vc4 + p * 128) << 2),
                         vsrc + vc4 + p * 128);
            }
            CP_COMMIT();
            const unsigned Ab = PS + (unsigned)(s >> 2) * 8192u;
            const int k8off = (s & 3) << 3;
            const unsigned vwbase = (unsigned)((s % 3) * (KV_STRIDE / 4));
            unsigned a[4][4];
            const int ca = (k8off + aoff) ^ xrA;
#pragma unroll
            for (int mi = 0; mi < 4; mi++)
                ldsm4(a[mi], Ab + ((((mi * 16 + rA) << 5) + ca) << 2));
#pragma unroll
            for (int ni = 0; ni < 8; ni++) {
                const int e = wne + ni * 8 + g;
                unsigned bv[2];
                bv[0] = Vw[vwbase + tg * 520 + e];
                bv[1] = Vw[vwbase + (tg + 4) * 520 + e];
#pragma unroll
                for (int mi = 0; mi < 4; mi++)
                    mma_tf32(O[mi][ni], a[mi], bv);
            }
        }
        __syncthreads();   // KV bufs free before next jt's K staging
    }

    // ---- epilogue: O / l, rounded ----
    float* Az = g_att + (size_t)z * NSEQ * DDIM;
#pragma unroll
    for (int mi = 0; mi < 4; mi++) {
        const float il0 = 1.f / lrow[mi * 16 + g];
        const float il1 = 1.f / lrow[mi * 16 + g + 8];
        float* r0 = Az + (size_t)(i0 + mi * 16 + g) * DDIM;
        float* r1 = r0 + (size_t)8 * DDIM;
#pragma unroll
        for (int ni = 0; ni < 8; ni++) {
            const int c = wne + ni * 8 + tg * 2;
            store2r(r0 + c, O[mi][ni][0] * il0, O[mi][ni][1] * il0);
            store2r(r1 + c, O[mi][ni][2] * il1, O[mi][ni][3] * il1);
        }
    }
}

// ---------------------------------------------------------------------------
// Output projection: out = cat_heads(att) @ Wo^T + bo
// ---------------------------------------------------------------------------
__global__ __launch_bounds__(NTHREADS, 2)
void outproj_kernel(const float* __restrict__ bo, float* __restrict__ out)
{
    extern __shared__ __align__(16) unsigned char smem[];
    const unsigned sbase = (unsigned)__cvta_generic_to_shared(smem);

    const int m0 = blockIdx.x * 128, dd0 = blockIdx.y * 128;
    const int bb = m0 / NSEQ, n0 = m0 % NSEQ;

    float acc[4][4][4];
    ZERO_ACC(acc);
    gemm_loop(sbase,
              g_att + (((size_t)bb * NHEAD + 0) * NSEQ + n0) * DDIM, DDIM,
              g_wot + (size_t)dd0 * (NHEAD * DDIM), NHEAD * DDIM,
              (NHEAD * DDIM) / 32, 15u, (size_t)NSEQ * DDIM - 480, acc);

    const int lane = threadIdx.x & 31, warp = threadIdx.x >> 5;
    const int wm = (warp >> 2) * 64, wn = (warp & 3) * 32;
    const int g = lane >> 2, tg = lane & 3;
#pragma unroll
    for (int mi = 0; mi < 4; mi++) {
        const int n = n0 + wm + mi * 16 + g;
#pragma unroll
        for (int ni = 0; ni < 4; ni++) {
            const int dd = dd0 + wn + ni * 8 + tg * 2;
            const float b0 = bo[dd], b1 = bo[dd + 1];
            *(float2*)(out + ((size_t)bb * NSEQ + n) * DDIM + dd) =
                make_float2(acc[mi][ni][0] + b0, acc[mi][ni][1] + b1);
            *(float2*)(out + ((size_t)bb * NSEQ + n + 8) * DDIM + dd) =
                make_float2(acc[mi][ni][2] + b0, acc[mi][ni][3] + b1);
        }
    }
}

// ---------------------------------------------------------------------------
extern "C" void kernel_launch(void* const* d_in, const int* in_sizes, int n_in,
                              void* d_out, int out_size)
{
    (void)in_sizes; (void)n_in; (void)out_size;
    const float* k_in = (const float*)d_in[0];
    const float* v_in = (const float*)d_in[1];
    const float* q_in = (const float*)d_in[2];
    const float* Wk   = (const float*)d_in[3];
    const float* bk   = (const float*)d_in[4];
    const float* Wv   = (const float*)d_in[5];
    const float* bv   = (const float*)d_in[6];
    const float* Wq   = (const float*)d_in[7];
    const float* bq   = (const float*)d_in[8];
    const float* Wo   = (const float*)d_in[9];
    const float* bo   = (const float*)d_in[10];
    float* out = (float*)d_out;

    cudaFuncSetAttribute((const void*)proj_kernel<0>, cudaFuncAttributeMaxDynamicSharedMemorySize, SMEM_BYTES);
    cudaFuncSetAttribute((const void*)proj_kernel<1>, cudaFuncAttributeMaxDynamicSharedMemorySize, SMEM_BYTES);
    cudaFuncSetAttribute((const void*)proj_kernel<2>, cudaFuncAttributeMaxDynamicSharedMemorySize, SMEM_BYTES);
    cudaFuncSetAttribute((const void*)flash_kernel,   cudaFuncAttributeMaxDynamicSharedMemorySize, SMEM_FLASH);
    cudaFuncSetAttribute((const void*)outproj_kernel, cudaFuncAttributeMaxDynamicSharedMemorySize, SMEM_BYTES);

    const int NXV4 = (BATCH * NSEQ * DDIM) / 4;
    const int NWV4 = (NHEAD * DDIM * DDIM) / 4;
    round_copy_kernel<0><<<(NXV4 + 255) / 256, 256>>>(k_in, NXV4);
    round_copy_kernel<1><<<(NXV4 + 255) / 256, 256>>>(v_in, NXV4);
    round_copy_kernel<2><<<(NXV4 + 255) / 256, 256>>>(q_in, NXV4);
    round_copy_kernel<3><<<(NWV4 + 255) / 256, 256>>>(Wk, NWV4);
    round_copy_kernel<4><<<(NWV4 + 255) / 256, 256>>>(Wv, NWV4);
    round_copy_kernel<5><<<(NWV4 + 255) / 256, 256>>>(Wq, NWV4);
    permute_wo_kernel<<<(NHEAD * DDIM * DDIM) / 256, 256>>>(Wo);

    dim3 gproj(BATCH * NSEQ / 128, DDIM / 128, NHEAD);
    proj_kernel<0><<<gproj, NTHREADS, SMEM_BYTES>>>(bk);
    proj_kernel<1><<<gproj, NTHREADS, SMEM_BYTES>>>(bv);
    proj_kernel<2><<<gproj, NTHREADS, SMEM_BYTES>>>(bq);

    // fused scores + softmax + P@V
    dim3 gflash(NSEQ / QB, BATCH * NHEAD, 1);
    flash_kernel<<<gflash, NTHREADS, SMEM_FLASH>>>();

    dim3 gout(BATCH * NSEQ / 128, DDIM / 128, 1);
    outproj_kernel<<<gout, NTHREADS, SMEM_BYTES>>>(bo, out);
}

// round 9
// speedup vs baseline: 1.1218x; 1.1218x over previous
#include <cuda_runtime.h>
#include <math.h>

// Problem constants
#define BATCH 32
#define NSEQ  1024
#define DDIM  512
#define NHEAD 8
#define SCALE 0.04419417382415922f   // 1/sqrt(512)

// ---------------------------------------------------------------------------
// Scratch (device globals; allocation-free per harness rules)
// ---------------------------------------------------------------------------
__device__ float g_kr [(size_t)BATCH * NSEQ * DDIM];          // rounded inputs
__device__ float g_vr [(size_t)BATCH * NSEQ * DDIM];
__device__ float g_qr [(size_t)BATCH * NSEQ * DDIM];
__device__ float g_wkr[(size_t)NHEAD * DDIM * DDIM];          // rounded weights
__device__ float g_wvr[(size_t)NHEAD * DDIM * DDIM];
__device__ float g_wqr[(size_t)NHEAD * DDIM * DDIM];
__device__ float g_kh [(size_t)BATCH * NHEAD * NSEQ * DDIM];  // projected K (rounded)
__device__ float g_qh [(size_t)BATCH * NHEAD * NSEQ * DDIM];  // projected Q (pre-scaled)
__device__ float g_vt [(size_t)BATCH * NHEAD * DDIM * NSEQ];  // projected V, transposed [z][e][j]
__device__ float g_s  [(size_t)BATCH * NHEAD * NSEQ * NSEQ];  // scores -> probs
__device__ float g_att[(size_t)BATCH * NHEAD * NSEQ * DDIM];  // attention out (rounded)
__device__ float g_wot[(size_t)NHEAD * DDIM * DDIM];          // Wo permuted [dd][h*D+e]

#define NTHREADS 256
#define STAGE_BYTES 32768u                 // A 16KB + B 16KB per stage
#define SMEM_BYTES (3 * STAGE_BYTES)       // 3-stage pipeline = 96KB

// ---------------------------------------------------------------------------
// Primitives
// ---------------------------------------------------------------------------
__device__ __forceinline__ unsigned f2tf(float f) {
    unsigned u;
    asm("cvt.rna.tf32.f32 %0, %1;" : "=r"(u) : "f"(f));
    return u;
}
__device__ __forceinline__ float rf(float f) { return __uint_as_float(f2tf(f)); }

__device__ __forceinline__ void store2r(float* p, float x, float y) {
    *(float2*)p = make_float2(rf(x), rf(y));
}

__device__ __forceinline__ void mma_tf32(float* d, const unsigned* a, const unsigned* b) {
    asm volatile(
        "mma.sync.aligned.m16n8k8.row.col.f32.tf32.tf32.f32 "
        "{%0,%1,%2,%3}, {%4,%5,%6,%7}, {%8,%9}, {%0,%1,%2,%3};\n"
        : "+f"(d[0]), "+f"(d[1]), "+f"(d[2]), "+f"(d[3])
        : "r"(a[0]), "r"(a[1]), "r"(a[2]), "r"(a[3]), "r"(b[0]), "r"(b[1]));
}

__device__ __forceinline__ void ldsm4(unsigned d[4], unsigned addr) {
    asm volatile("ldmatrix.sync.aligned.m8n8.x4.shared.b16 {%0,%1,%2,%3}, [%4];"
                 : "=r"(d[0]), "=r"(d[1]), "=r"(d[2]), "=r"(d[3]) : "r"(addr));
}

__device__ __forceinline__ void cp16(unsigned dst, const float* src) {
    asm volatile("cp.async.cg.shared.global [%0], [%1], 16;" :: "r"(dst), "l"(src));
}
#define CP_COMMIT() asm volatile("cp.async.commit_group;")
#define CP_WAIT1()  asm volatile("cp.async.wait_group 1;")

#define ZERO_ACC(acc)                          \
    _Pragma("unroll")                          \
    for (int mi = 0; mi < 4; mi++)             \
    _Pragma("unroll")                          \
    for (int ni = 0; ni < 4; ni++)             \
    _Pragma("unroll")                          \
    for (int q = 0; q < 4; q++) acc[mi][ni][q] = 0.f;

// ---------------------------------------------------------------------------
// Staging: one 128-row x 32-word tile via cp.async, XOR-4 swizzled.
// ---------------------------------------------------------------------------
__device__ __forceinline__ void stage_tile(unsigned sb, const float* src, size_t ld,
                                           int sr, int sc4, int xs) {
#pragma unroll
    for (int p = 0; p < 4; p++) {
        const int r = sr + p * 32;
        const unsigned dst = sb + (((r << 5) + (sc4 ^ xs)) << 2);
        cp16(dst, src + (size_t)r * ld + sc4);
    }
}

// ---------------------------------------------------------------------------
// Compute one staged 128x128x32 tile. Warp tile 64x32 (8 warps, 2m x 4n).
// ---------------------------------------------------------------------------
__device__ __forceinline__ void tile_compute(unsigned bufA, float acc[4][4][4],
                                             int wm, int wn, int rA, int aoff, int xrA,
                                             int rB, int boff, int xrB) {
    const unsigned bufB = bufA + 16384u;
#pragma unroll
    for (int ks = 0; ks < 4; ks++) {
        unsigned a[4][4], b[2][4];
        const int ca = ((ks << 3) + aoff) ^ xrA;
        const int cb = ((ks << 3) + boff) ^ xrB;
#pragma unroll
        for (int mi = 0; mi < 4; mi++)
            ldsm4(a[mi], bufA + ((((wm + mi * 16 + rA) << 5) + ca) << 2));
#pragma unroll
        for (int p = 0; p < 2; p++)
            ldsm4(b[p], bufB + ((((wn + p * 16 + rB) << 5) + cb) << 2));
#pragma unroll
        for (int mi = 0; mi < 4; mi++)
#pragma unroll
            for (int ni = 0; ni < 4; ni++)
                mma_tf32(acc[mi][ni], a[mi], &b[ni >> 1][(ni & 1) << 1]);
    }
}

// ---------------------------------------------------------------------------
// GEMM mainloop: 3-stage cp.async pipeline, one sync per k-tile (R5, proven).
// ---------------------------------------------------------------------------
__device__ __forceinline__ void gemm_loop(unsigned sbase,
                                          const float* pA, size_t ldA,
                                          const float* pB, size_t ldB,
                                          int KT, unsigned aMask, size_t aBig,
                                          float acc[4][4][4]) {
    const int tid = threadIdx.x;
    const int lane = tid & 31, warp = tid >> 5;
    const int wm = (warp >> 2) * 64, wn = (warp & 3) * 32;
    const int sr = tid >> 3, sc4 = (tid & 7) << 2, xs = (sr & 7) << 2;
    const int rA = lane & 15;
    const int aoff = (lane >> 4) << 2;
    const int xrA = (rA & 7) << 2;
    const int rB = ((lane >> 4) << 3) + (lane & 7);
    const int boff = ((lane >> 3) & 1) << 2;
    const int xrB = (lane & 7) << 2;

    unsigned s0 = sbase, s1 = sbase + STAGE_BYTES, s2 = sbase + 2 * STAGE_BYTES;

    stage_tile(s0, pA, ldA, sr, sc4, xs);
    stage_tile(s0 + 16384u, pB, ldB, sr, sc4, xs);
    CP_COMMIT();
    pA += ((1u & aMask) == 0u) ? aBig : 32;
    pB += 32;
    stage_tile(s1, pA, ldA, sr, sc4, xs);
    stage_tile(s1 + 16384u, pB, ldB, sr, sc4, xs);
    CP_COMMIT();

    for (int kt = 0; kt < KT; kt++) {
        CP_WAIT1();
        __syncthreads();
        if (kt + 2 < KT) {
            pA += (((unsigned)(kt + 2) & aMask) == 0u) ? aBig : 32;
            pB += 32;
            stage_tile(s2, pA, ldA, sr, sc4, xs);
            stage_tile(s2 + 16384u, pB, ldB, sr, sc4, xs);
        }
        CP_COMMIT();
        tile_compute(s0, acc, wm, wn, rA, aoff, xrA, rB, boff, xrB);
        const unsigned t = s0; s0 = s1; s1 = s2; s2 = t;
    }
}

// ---------------------------------------------------------------------------
// Pre-pass: batched round-copies (3 tensors per kernel via blockIdx.y)
// ---------------------------------------------------------------------------
__global__ void round_inputs_kernel(const float* __restrict__ k,
                                    const float* __restrict__ v,
                                    const float* __restrict__ q, int n4)
{
    const int t = blockIdx.y;
    const float* src = (t == 0) ? k : (t == 1) ? v : q;
    float* dst = (t == 0) ? g_kr : (t == 1) ? g_vr : g_qr;
    int i = blockIdx.x * blockDim.x + threadIdx.x;
    if (i < n4) {
        float4 x = ((const float4*)src)[i];
        ((float4*)dst)[i] = make_float4(rf(x.x), rf(x.y), rf(x.z), rf(x.w));
    }
}

__global__ void round_weights_kernel(const float* __restrict__ Wk,
                                     const float* __restrict__ Wv,
                                     const float* __restrict__ Wq, int n4)
{
    const int t = blockIdx.y;
    const float* src = (t == 0) ? Wk : (t == 1) ? Wv : Wq;
    float* dst = (t == 0) ? g_wkr : (t == 1) ? g_wvr : g_wqr;
    int i = blockIdx.x * blockDim.x + threadIdx.x;
    if (i < n4) {
        float4 x = ((const float4*)src)[i];
        ((float4*)dst)[i] = make_float4(rf(x.x), rf(x.y), rf(x.z), rf(x.w));
    }
}

__global__ void permute_wo_kernel(const float* __restrict__ Wo)
{
    int idx = blockIdx.x * blockDim.x + threadIdx.x;   // dd*4096 + h*512 + e
    int t  = idx & (NHEAD * DDIM - 1);
    int dd = idx >> 12;
    int e  = t & (DDIM - 1);
    int h  = t >> 9;
    g_wot[idx] = rf(Wo[(size_t)dd * (NHEAD * DDIM) + e * NHEAD + h]);
}

// ---------------------------------------------------------------------------
// Projection (NT): Y = X.W^T + bias, rounded.
//   P==0 -> g_kh (row layout), P==2 -> g_qh (row layout, pre-scaled by 1/sqrt(D)),
//   P==1 -> g_vt DIRECTLY TRANSPOSED: vt[z][e][j]  (fuses the old transpose pass)
// grid: (B*N/128, D/128, H)
// ---------------------------------------------------------------------------
template <int P>
__global__ __launch_bounds__(NTHREADS, 2)
void proj_kernel(const float* __restrict__ bias)
{
    extern __shared__ __align__(16) unsigned char smem[];
    const unsigned sbase = (unsigned)__cvta_generic_to_shared(smem);

    const float* X = (P == 0) ? g_kr : (P == 1) ? g_vr : g_qr;
    const float* W = (P == 0) ? g_wkr : (P == 1) ? g_wvr : g_wqr;
    const float ps = (P == 2) ? SCALE : 1.0f;

    const int h = blockIdx.z, m0 = blockIdx.x * 128, e0 = blockIdx.y * 128;

    float acc[4][4][4];
    ZERO_ACC(acc);
    gemm_loop(sbase, X + (size_t)m0 * DDIM, DDIM,
              W + (size_t)h * DDIM * DDIM + (size_t)e0 * DDIM, DDIM,
              DDIM / 32, 0u, 32, acc);

    const int lane = threadIdx.x & 31, warp = threadIdx.x >> 5;
    const int wm = (warp >> 2) * 64, wn = (warp & 3) * 32;
    const int g = lane >> 2, tg = lane & 3;
    const int bb = m0 / NSEQ, n0 = m0 % NSEQ;
    const size_t z = (size_t)bb * NHEAD + h;
    const float* bh = bias + h * DDIM + e0;

    if (P == 1) {
        // Transposed store: vt[(z*D + e)*N + j], j = n0 + r.
        float* Vt = g_vt + z * DDIM * NSEQ;
#pragma unroll
        for (int mi = 0; mi < 4; mi++) {
            const int r = wm + mi * 16 + g;
            const int j0a = n0 + r, j0b = n0 + r + 8;
#pragma unroll
            for (int ni = 0; ni < 4; ni++) {
                const int c = wn + ni * 8 + tg * 2;
                const float b0 = bh[c], b1 = bh[c + 1];
                float* col0 = Vt + (size_t)(e0 + c) * NSEQ;
                float* col1 = Vt + (size_t)(e0 + c + 1) * NSEQ;
                col0[j0a] = rf(acc[mi][ni][0] + b0);
                col1[j0a] = rf(acc[mi][ni][1] + b1);
                col0[j0b] = rf(acc[mi][ni][2] + b0);
                col1[j0b] = rf(acc[mi][ni][3] + b1);
            }
        }
    } else {
        float* Y = (P == 0) ? g_kh : g_qh;
        float* Yb = Y + (z * NSEQ + n0) * DDIM + e0;
#pragma unroll
        for (int mi = 0; mi < 4; mi++) {
            const int r = wm + mi * 16 + g;
#pragma unroll
            for (int ni = 0; ni < 4; ni++) {
                const int c = wn + ni * 8 + tg * 2;
                const float b0 = bh[c], b1 = bh[c + 1];
                store2r(Yb + (size_t)r * DDIM + c,
                        (acc[mi][ni][0] + b0) * ps, (acc[mi][ni][1] + b1) * ps);
                store2r(Yb + (size_t)(r + 8) * DDIM + c,
                        (acc[mi][ni][2] + b0) * ps, (acc[mi][ni][3] + b1) * ps);
            }
        }
    }
}

// ---------------------------------------------------------------------------
// scores (NT): S[z,i,j] = qh[z,i,:].kh[z,j,:]  (qh pre-scaled)
// grid: (N/128, N/128, B*H)
// ---------------------------------------------------------------------------
__global__ __launch_bounds__(NTHREADS, 2)
void scores_kernel()
{
    extern __shared__ __align__(16) unsigned char smem[];
    const unsigned sbase = (unsigned)__cvta_generic_to_shared(smem);

    const size_t zb = (size_t)blockIdx.z * NSEQ * DDIM;
    const int m0 = blockIdx.x * 128, j0 = blockIdx.y * 128;
    float* S = g_s + (size_t)blockIdx.z * NSEQ * NSEQ;

    float acc[4][4][4];
    ZERO_ACC(acc);
    gemm_loop(sbase, g_qh + zb + (size_t)m0 * DDIM, DDIM,
              g_kh + zb + (size_t)j0 * DDIM, DDIM,
              DDIM / 32, 0u, 32, acc);

    const int lane = threadIdx.x & 31, warp = threadIdx.x >> 5;
    const int wm = (warp >> 2) * 64, wn = (warp & 3) * 32;
    const int g = lane >> 2, tg = lane & 3;
#pragma unroll
    for (int mi = 0; mi < 4; mi++) {
        const int r = m0 + wm + mi * 16 + g;
#pragma unroll
        for (int ni = 0; ni < 4; ni++) {
            const int c = j0 + wn + ni * 8 + tg * 2;
            *(float2*)(S + (size_t)r * NSEQ + c) =
                make_float2(acc[mi][ni][0], acc[mi][ni][1]);
            *(float2*)(S + (size_t)(r + 8) * NSEQ + c) =
                make_float2(acc[mi][ni][2], acc[mi][ni][3]);
        }
    }
}

// ---------------------------------------------------------------------------
// in-place row softmax, output rounded to tf32
// ---------------------------------------------------------------------------
__global__ __launch_bounds__(128)
void softmax_kernel()
{
    float* row = g_s + (size_t)blockIdx.x * NSEQ;
    const int tid = threadIdx.x;
    __shared__ float sm1[4], sm2[4];

    float v[8];
    float mx = -1e30f;
#pragma unroll
    for (int r = 0; r < 8; r++) { v[r] = row[tid + r * 128]; mx = fmaxf(mx, v[r]); }
#pragma unroll
    for (int o = 16; o; o >>= 1) mx = fmaxf(mx, __shfl_xor_sync(0xffffffffu, mx, o));
    if ((tid & 31) == 0) sm1[tid >> 5] = mx;
    __syncthreads();
    mx = fmaxf(fmaxf(sm1[0], sm1[1]), fmaxf(sm1[2], sm1[3]));

    float s = 0.f;
#pragma unroll
    for (int r = 0; r < 8; r++) { v[r] = __expf(v[r] - mx); s += v[r]; }
#pragma unroll
    for (int o = 16; o; o >>= 1) s += __shfl_xor_sync(0xffffffffu, s, o);
    if ((tid & 31) == 0) sm2[tid >> 5] = s;
    __syncthreads();
    s = sm2[0] + sm2[1] + sm2[2] + sm2[3];

    const float inv = 1.f / s;
#pragma unroll
    for (int r = 0; r < 8; r++) row[tid + r * 128] = rf(v[r] * inv);
}

// ---------------------------------------------------------------------------
// attout: att[z,i,e] = sum_j probs[z,i,j] * vt[z,e,j]  (rounded)
// grid: (N/128, D/128, B*H)
// ---------------------------------------------------------------------------
__global__ __launch_bounds__(NTHREADS, 2)
void attout_kernel()
{
    extern __shared__ __align__(16) unsigned char smem[];
    const unsigned sbase = (unsigned)__cvta_generic_to_shared(smem);

    const int m0 = blockIdx.x * 128, e0 = blockIdx.y * 128;
    const float* Pz = g_s + (size_t)blockIdx.z * NSEQ * NSEQ + (size_t)m0 * NSEQ;
    const float* Vt = g_vt + (size_t)blockIdx.z * NSEQ * DDIM + (size_t)e0 * NSEQ;
    float* Az = g_att + (size_t)blockIdx.z * NSEQ * DDIM;

    float acc[4][4][4];
    ZERO_ACC(acc);
    gemm_loop(sbase, Pz, NSEQ, Vt, NSEQ, NSEQ / 32, 0u, 32, acc);

    const int lane = threadIdx.x & 31, warp = threadIdx.x >> 5;
    const int wm = (warp >> 2) * 64, wn = (warp & 3) * 32;
    const int g = lane >> 2, tg = lane & 3;
#pragma unroll
    for (int mi = 0; mi < 4; mi++) {
        const int r = m0 + wm + mi * 16 + g;
#pragma unroll
        for (int ni = 0; ni < 4; ni++) {
            const int c = e0 + wn + ni * 8 + tg * 2;
            store2r(Az + (size_t)r * DDIM + c, acc[mi][ni][0], acc[mi][ni][1]);
            store2r(Az + (size_t)(r + 8) * DDIM + c, acc[mi][ni][2], acc[mi][ni][3]);
        }
    }
}

// ---------------------------------------------------------------------------
// outproj: out[b,n,dd] = sum_{h,e} att[b,h,n,e]*wot[dd,h*D+e] + bo
// grid: (B*N/128, D/128). A head-chunked (jump every 16 k-tiles).
// ---------------------------------------------------------------------------
__global__ __launch_bounds__(NTHREADS, 2)
void outproj_kernel(const float* __restrict__ bo, float* __restrict__ out)
{
    extern __shared__ __align__(16) unsigned char smem[];
    const unsigned sbase = (unsigned)__cvta_generic_to_shared(smem);

    const int m0 = blockIdx.x * 128, dd0 = blockIdx.y * 128;
    const int bb = m0 / NSEQ, n0 = m0 % NSEQ;

    float acc[4][4][4];
    ZERO_ACC(acc);
    gemm_loop(sbase,
              g_att + (((size_t)bb * NHEAD + 0) * NSEQ + n0) * DDIM, DDIM,
              g_wot + (size_t)dd0 * (NHEAD * DDIM), NHEAD * DDIM,
              (NHEAD * DDIM) / 32, 15u, (size_t)NSEQ * DDIM - 480, acc);

    const int lane = threadIdx.x & 31, warp = threadIdx.x >> 5;
    const int wm = (warp >> 2) * 64, wn = (warp & 3) * 32;
    const int g = lane >> 2, tg = lane & 3;
#pragma unroll
    for (int mi = 0; mi < 4; mi++) {
        const int n = n0 + wm + mi * 16 + g;
#pragma unroll
        for (int ni = 0; ni < 4; ni++) {
            const int dd = dd0 + wn + ni * 8 + tg * 2;
            const float b0 = bo[dd], b1 = bo[dd + 1];
            *(float2*)(out + ((size_t)bb * NSEQ + n) * DDIM + dd) =
                make_float2(acc[mi][ni][0] + b0, acc[mi][ni][1] + b1);
            *(float2*)(out + ((size_t)bb * NSEQ + n + 8) * DDIM + dd) =
                make_float2(acc[mi][ni][2] + b0, acc[mi][ni][3] + b1);
        }
    }
}

// ---------------------------------------------------------------------------
extern "C" void kernel_launch(void* const* d_in, const int* in_sizes, int n_in,
                              void* d_out, int out_size)
{
    (void)in_sizes; (void)n_in; (void)out_size;
    const float* k_in = (const float*)d_in[0];
    const float* v_in = (const float*)d_in[1];
    const float* q_in = (const float*)d_in[2];
    const float* Wk   = (const float*)d_in[3];
    const float* bk   = (const float*)d_in[4];
    const float* Wv   = (const float*)d_in[5];
    const float* bv   = (const float*)d_in[6];
    const float* Wq   = (const float*)d_in[7];
    const float* bq   = (const float*)d_in[8];
    const float* Wo   = (const float*)d_in[9];
    const float* bo   = (const float*)d_in[10];
    float* out = (float*)d_out;

    cudaFuncSetAttribute((const void*)proj_kernel<0>, cudaFuncAttributeMaxDynamicSharedMemorySize, SMEM_BYTES);
    cudaFuncSetAttribute((const void*)proj_kernel<1>, cudaFuncAttributeMaxDynamicSharedMemorySize, SMEM_BYTES);
    cudaFuncSetAttribute((const void*)proj_kernel<2>, cudaFuncAttributeMaxDynamicSharedMemorySize, SMEM_BYTES);
    cudaFuncSetAttribute((const void*)scores_kernel,  cudaFuncAttributeMaxDynamicSharedMemorySize, SMEM_BYTES);
    cudaFuncSetAttribute((const void*)attout_kernel,  cudaFuncAttributeMaxDynamicSharedMemorySize, SMEM_BYTES);
    cudaFuncSetAttribute((const void*)outproj_kernel, cudaFuncAttributeMaxDynamicSharedMemorySize, SMEM_BYTES);

    // Launch order puts proj_kernel<2> at index 5 so ncu (-s 5 -c 1) profiles a GEMM.
    const int NXV4 = (BATCH * NSEQ * DDIM) / 4;
    const int NWV4 = (NHEAD * DDIM * DDIM) / 4;
    round_inputs_kernel<<<dim3((NXV4 + 255) / 256, 3), 256>>>(k_in, v_in, q_in, NXV4);   // 0
    round_weights_kernel<<<dim3((NWV4 + 255) / 256, 3), 256>>>(Wk, Wv, Wq, NWV4);        // 1
    permute_wo_kernel<<<(NHEAD * DDIM * DDIM) / 256, 256>>>(Wo);                         // 2

    dim3 gproj(BATCH * NSEQ / 128, DDIM / 128, NHEAD);
    proj_kernel<0><<<gproj, NTHREADS, SMEM_BYTES>>>(bk);                                 // 3
    proj_kernel<1><<<gproj, NTHREADS, SMEM_BYTES>>>(bv);                                 // 4 (writes g_vt)
    proj_kernel<2><<<gproj, NTHREADS, SMEM_BYTES>>>(bq);                                 // 5 <- profiled

    dim3 gsc(NSEQ / 128, NSEQ / 128, BATCH * NHEAD);
    scores_kernel<<<gsc, NTHREADS, SMEM_BYTES>>>();                                      // 6

    softmax_kernel<<<BATCH * NHEAD * NSEQ, 128>>>();                                     // 7

    dim3 gatt(NSEQ / 128, DDIM / 128, BATCH * NHEAD);
    attout_kernel<<<gatt, NTHREADS, SMEM_BYTES>>>();                                     // 8

    dim3 gout(BATCH * NSEQ / 128, DDIM / 128, 1);
    outproj_kernel<<<gout, NTHREADS, SMEM_BYTES>>>(bo, out);                             // 9
}